// round 1
// baseline (speedup 1.0000x reference)
#include <cuda_runtime.h>
#include <cstdint>

// out[b,c,i,j] = x[b,c, i^3, j^3]   (H = W = 256, both divisible by 4)
//
// j^3 within an aligned group of 4 floats = lane-reverse of a float4.
// i^3 is a row shuffle; rows are contiguous so both load and store are
// fully coalesced 16B accesses.

static constexpr int W4 = 64;   // 256 / 4 float4s per row
static constexpr int H  = 256;

__global__ void __launch_bounds__(256)
dualswitch_kernel(const float4* __restrict__ in, float4* __restrict__ out, int total4) {
    int idx = blockIdx.x * blockDim.x + threadIdx.x;
    if (idx >= total4) return;

    // idx = ((bc * H) + i) * W4 + g    (all powers of two -> shifts/ands)
    int g    = idx & (W4 - 1);
    int rest = idx >> 6;           // / W4
    int i    = rest & (H - 1);
    int bc   = rest >> 8;          // / H

    int in_idx = ((bc << 8) | (i ^ 3)) * W4 + g;

    float4 v = in[in_idx];
    out[idx] = make_float4(v.w, v.z, v.y, v.x);   // j^3 lane reverse
}

extern "C" void kernel_launch(void* const* d_in, const int* in_sizes, int n_in,
                              void* d_out, int out_size) {
    const float4* in  = (const float4*)d_in[0];
    float4*       out = (float4*)d_out;
    int total4 = out_size / 4;                     // 25,165,824
    int threads = 256;
    int blocks  = (total4 + threads - 1) / threads;
    dualswitch_kernel<<<blocks, threads>>>(in, out, total4);
}

// round 2
// speedup vs baseline: 1.0089x; 1.0089x over previous
#include <cuda_runtime.h>
#include <cstdint>

// out[b,c,i,j] = x[b,c, i^3, j^3]   (H = W = 256)
// j^3 within an aligned float4 = lane reverse; i^3 = row shuffle.
// 4 float4s per thread (front-batched independent LDG.128 -> MLP=4/thread),
// streaming cache hints (no reuse, evict-first).

static constexpr int W4 = 64;    // float4s per row
static constexpr int H  = 256;
static constexpr int UNROLL = 4;

__global__ void __launch_bounds__(256)
dualswitch_kernel(const float4* __restrict__ in, float4* __restrict__ out) {
    // Each block owns a contiguous chunk of 256*UNROLL float4s.
    int base = blockIdx.x * (256 * UNROLL) + threadIdx.x;

    float4 v[UNROLL];
    #pragma unroll
    for (int u = 0; u < UNROLL; u++) {
        int idx  = base + u * 256;
        int g    = idx & (W4 - 1);
        int rest = idx >> 6;
        int i    = rest & (H - 1);
        int bc   = rest >> 8;
        int in_idx = ((bc << 8) | (i ^ 3)) * W4 + g;
        v[u] = __ldcs(in + in_idx);
    }

    #pragma unroll
    for (int u = 0; u < UNROLL; u++) {
        int idx = base + u * 256;
        __stcs(out + idx, make_float4(v[u].w, v[u].z, v[u].y, v[u].x));
    }
}

extern "C" void kernel_launch(void* const* d_in, const int* in_sizes, int n_in,
                              void* d_out, int out_size) {
    const float4* in  = (const float4*)d_in[0];
    float4*       out = (float4*)d_out;
    int total4 = out_size / 4;                     // 25,165,824
    int blocks = total4 / (256 * UNROLL);          // exact: 24,576
    dualswitch_kernel<<<blocks, 256>>>(in, out);
}

// round 3
// speedup vs baseline: 1.0092x; 1.0003x over previous
#include <cuda_runtime.h>
#include <cstdint>

// out[b,c,i,j] = x[b,c, i^3, j^3]   (H = W = 256)
// j^3 within an aligned float4 = lane reverse; i^3 = row shuffle.
// 8 float4s per thread, front-batched independent LDG.128 (MLP=8/thread),
// streaming cache hints (evict-first; zero reuse).

static constexpr int W4 = 64;    // float4s per row
static constexpr int H  = 256;
static constexpr int UNROLL = 8;

__global__ void __launch_bounds__(256)
dualswitch_kernel(const float4* __restrict__ in, float4* __restrict__ out) {
    // Each block owns a contiguous chunk of 256*UNROLL float4s.
    int base = blockIdx.x * (256 * UNROLL) + threadIdx.x;

    float4 v[UNROLL];
    #pragma unroll
    for (int u = 0; u < UNROLL; u++) {
        int idx  = base + u * 256;
        int g    = idx & (W4 - 1);
        int rest = idx >> 6;
        int i    = rest & (H - 1);
        int bc   = rest >> 8;
        int in_idx = ((bc << 8) | (i ^ 3)) * W4 + g;
        v[u] = __ldcs(in + in_idx);
    }

    #pragma unroll
    for (int u = 0; u < UNROLL; u++) {
        int idx = base + u * 256;
        __stcs(out + idx, make_float4(v[u].w, v[u].z, v[u].y, v[u].x));
    }
}

extern "C" void kernel_launch(void* const* d_in, const int* in_sizes, int n_in,
                              void* d_out, int out_size) {
    const float4* in  = (const float4*)d_in[0];
    float4*       out = (float4*)d_out;
    int total4 = out_size / 4;                     // 25,165,824
    int blocks = total4 / (256 * UNROLL);          // exact: 12,288
    dualswitch_kernel<<<blocks, 256>>>(in, out);
}